// round 9
// baseline (speedup 1.0000x reference)
#include <cuda_runtime.h>
#include <math.h>

#define TT 256
#define BSZ 256

// ---------------- device scratch (no allocation APIs) ----------------
static __device__ float g_xg0f[33554432];   // [T*B][512]
static __device__ float g_xg0r[33554432];   // [T*B][512]
static __device__ float g_xg1 [67108864];   // [T*B][1024] (layer1, reused layer2)
static __device__ float g_bl  [16777216];   // [T*B][256]  bilstm h -> LN1 in place
static __device__ float g_h1  [16777216];   // [T*B][256]  layer1 h -> LN2 in place
static __device__ float g_h2  [16777216];   // [T*B][256]  layer2 h
static __device__ int   g_flags[16384];

__global__ void zero_flags_kernel() {
    int i = blockIdx.x * blockDim.x + threadIdx.x;
    if (i < 16384) g_flags[i] = 0;
}

// ---------------- tf32 helpers ----------------
__device__ __forceinline__ unsigned f2tf32(float x) {
    unsigned r;
    asm("cvt.rna.tf32.f32 %0, %1;" : "=r"(r) : "f"(x));
    return r;
}
__device__ __forceinline__ void mma_tf32(float c[4], const unsigned a[4], const unsigned b[2]) {
    asm volatile(
        "mma.sync.aligned.m16n8k8.row.col.f32.tf32.tf32.f32 "
        "{%0,%1,%2,%3}, {%4,%5,%6,%7}, {%8,%9}, {%0,%1,%2,%3};"
        : "+f"(c[0]), "+f"(c[1]), "+f"(c[2]), "+f"(c[3])
        : "r"(a[0]), "r"(a[1]), "r"(a[2]), "r"(a[3]), "r"(b[0]), "r"(b[1]));
}

// packed fp32x2 fma: acc += a * b (elementwise on packed pairs)
__device__ __forceinline__ void fma2(unsigned long long& acc,
                                     unsigned long long a, unsigned long long b) {
    asm("fma.rn.f32x2 %0, %1, %2, %0;" : "+l"(acc) : "l"(a), "l"(b));
}
__device__ __forceinline__ float hsum2(unsigned long long v) {
    float2 f = *(float2*)&v;
    return f.x + f.y;
}

// ---------------- tf32 tensor-core GEMM: C[M,N] = A[M,K] @ W[N,K]^T + bias ----
template<int K, int N, int MODE>
__global__ void __launch_bounds__(256) mma_gemm(const float* __restrict__ Ap,
                                                const float* __restrict__ W,
                                                const float* __restrict__ bias)
{
    __shared__ unsigned As[128 * 36];
    __shared__ unsigned Bs[128 * 36];
    const int tid = threadIdx.x, lane = tid & 31, wid = tid >> 5;
    const int warpM = wid >> 1, warpN = wid & 1;
    const int cRow = blockIdx.x, cCol = blockIdx.y;

    float acc[2][8][4];
#pragma unroll
    for (int mt = 0; mt < 2; mt++)
#pragma unroll
        for (int nt = 0; nt < 8; nt++)
#pragma unroll
            for (int i = 0; i < 4; i++) acc[mt][nt][i] = 0.f;

    for (int kt = 0; kt < K; kt += 32) {
#pragma unroll
        for (int i = 0; i < 4; i++) {
            int f = tid + i * 256;
            int row = f >> 3, kc = (f & 7) << 2;
            const float* ap;
            if (MODE <= 1) {
                int m = cRow * 128 + row;
                ap = Ap + ((size_t)(m & 255) * TT + (m >> 8)) * 128 + kt + kc;
            } else if (MODE == 2) {
                ap = g_bl + (size_t)(cRow * 128 + row) * K + kt + kc;
            } else {
                ap = g_h1 + (size_t)(cRow * 128 + row) * K + kt + kc;
            }
            float4 av = *(const float4*)ap;
            float4 bv = *(const float4*)(W + (size_t)(cCol * 128 + row) * K + kt + kc);
            unsigned* ad = &As[row * 36 + kc];
            ad[0] = f2tf32(av.x); ad[1] = f2tf32(av.y);
            ad[2] = f2tf32(av.z); ad[3] = f2tf32(av.w);
            unsigned* bd = &Bs[row * 36 + kc];
            bd[0] = f2tf32(bv.x); bd[1] = f2tf32(bv.y);
            bd[2] = f2tf32(bv.z); bd[3] = f2tf32(bv.w);
        }
        __syncthreads();

#pragma unroll
        for (int kk = 0; kk < 32; kk += 8) {
            const int k0 = kk + (lane & 3);
            unsigned a[2][4], b[8][2];
#pragma unroll
            for (int mt = 0; mt < 2; mt++) {
                int row = warpM * 32 + mt * 16 + (lane >> 2);
                a[mt][0] = As[row * 36 + k0];
                a[mt][1] = As[(row + 8) * 36 + k0];
                a[mt][2] = As[row * 36 + k0 + 4];
                a[mt][3] = As[(row + 8) * 36 + k0 + 4];
            }
#pragma unroll
            for (int nt = 0; nt < 8; nt++) {
                int col = warpN * 64 + nt * 8 + (lane >> 2);
                b[nt][0] = Bs[col * 36 + k0];
                b[nt][1] = Bs[col * 36 + k0 + 4];
            }
#pragma unroll
            for (int mt = 0; mt < 2; mt++)
#pragma unroll
                for (int nt = 0; nt < 8; nt++)
                    mma_tf32(acc[mt][nt], a[mt], b[nt]);
        }
        __syncthreads();
    }

    float* Cout = (MODE == 0) ? g_xg0f : (MODE == 1) ? g_xg0r : g_xg1;
#pragma unroll
    for (int nt = 0; nt < 8; nt++) {
        int c = cCol * 128 + warpN * 64 + nt * 8 + (lane & 3) * 2;
        float bx = bias[c], by = bias[c + 1];
#pragma unroll
        for (int mt = 0; mt < 2; mt++) {
            int r0 = cRow * 128 + warpM * 32 + mt * 16 + (lane >> 2);
            float2 o0 = {acc[mt][nt][0] + bx, acc[mt][nt][1] + by};
            float2 o1 = {acc[mt][nt][2] + bx, acc[mt][nt][3] + by};
            *(float2*)(Cout + (size_t)r0 * N + c)       = o0;
            *(float2*)(Cout + (size_t)(r0 + 8) * N + c) = o1;
        }
    }
}

__device__ __forceinline__ float sigf(float x) { return 1.f / (1.f + expf(-x)); }

// ---------------- layer0 persistent scan, H=128, grid (16,4,2) ----------------
// j-split warps: lane = (jh<<4)|b ; warp owns a j-quad. Weight LDS are
// broadcast (all 8 lanes of a phase share the address); h LDS conflict-free.
// Packed f32x2 FMA over the k dimension.
__global__ void __launch_bounds__(256) scan0_kernel(const float* __restrict__ WhhF,
                                                    const float* __restrict__ WhhR)
{
    const int bi = blockIdx.x, jj = blockIdx.y, dir = blockIdx.z;
    const int tid = threadIdx.x, lane = tid & 31, w = tid >> 5;
    const int b = lane & 15, jh = lane >> 4;
    const int jloc = w * 4 + jh * 2;          // even, 0..30
    const int j0 = jj * 32, b0 = bi * 16;
    const int HP = 132;

    extern __shared__ float sm[];
    float* Wsm = sm;               // [128 rows (g*32+jl)][128]
    float* hsm = sm + 128 * 128;   // [16][132]

    const float* Whh = dir ? WhhR : WhhF;
    const float* xg  = dir ? g_xg0r : g_xg0f;
    int* flags = g_flags + dir * 4096 + bi * 256;

    for (int v = tid; v < 128 * 32; v += 256) {
        int r = v >> 5, kc = (v & 31) << 2;
        int grow = ((r >> 5) << 7) + j0 + (r & 31);
        *(float4*)&Wsm[r * 128 + kc] = *(const float4*)(Whh + (size_t)grow * 128 + kc);
    }
    __syncthreads();

    float c0 = 0.f, c1 = 0.f;
    for (int s = 0; s < 256; s++) {
        const int t = dir ? (255 - s) : s;

        // preload input-gate values: per gate a float2 covering the j-pair
        float2 xv[4];
        {
            const float* xr = xg + ((size_t)(t * 256 + b0 + b)) * 512 + j0 + jloc;
#pragma unroll
            for (int g = 0; g < 4; g++) xv[g] = *(const float2*)(xr + (g << 7));
        }

        float gate[8];   // [jp*4+g]
#pragma unroll
        for (int g = 0; g < 4; g++) { gate[g] = xv[g].x; gate[4 + g] = xv[g].y; }

        if (s > 0) {
            const int tp = dir ? (t + 1) : (t - 1);
            if (tid == 0) { while (*(volatile int*)&flags[s - 1] < 4) { } }
            __syncthreads();
            for (int v = tid; v < 512; v += 256) {
                int row = v >> 5, kc = (v & 31) << 2;
                *(float4*)&hsm[row * HP + kc] =
                    *(const float4*)(g_bl + ((size_t)(tp * 256 + b0 + row)) * 256 + (dir << 7) + kc);
            }
            __syncthreads();

            unsigned long long acc[8];
#pragma unroll
            for (int i = 0; i < 8; i++) acc[i] = 0ull;

            const float* hrow = &hsm[b * HP];
#pragma unroll 2
            for (int k = 0; k < 128; k += 4) {
                ulonglong2 hv = *(const ulonglong2*)(hrow + k);
#pragma unroll
                for (int g = 0; g < 4; g++) {
#pragma unroll
                    for (int jp = 0; jp < 2; jp++) {
                        ulonglong2 wv = *(const ulonglong2*)&Wsm[((g << 5) + jloc + jp) * 128 + k];
                        fma2(acc[jp * 4 + g], wv.x, hv.x);
                        fma2(acc[jp * 4 + g], wv.y, hv.y);
                    }
                }
            }
#pragma unroll
            for (int i = 0; i < 8; i++) gate[i] += hsum2(acc[i]);
        }

        float2 ho;
        {
            float iv = sigf(gate[0]), fv = sigf(gate[1]);
            float gv = tanhf(gate[2]), ov = sigf(gate[3]);
            c0 = fv * c0 + iv * gv;
            ho.x = ov * tanhf(c0);
        }
        {
            float iv = sigf(gate[4]), fv = sigf(gate[5]);
            float gv = tanhf(gate[6]), ov = sigf(gate[7]);
            c1 = fv * c1 + iv * gv;
            ho.y = ov * tanhf(c1);
        }
        *(float2*)(g_bl + ((size_t)(t * 256 + b0 + b)) * 256 + (dir << 7) + j0 + jloc) = ho;

        __threadfence();
        __syncthreads();
        if (tid == 0) atomicAdd(&flags[s], 1);
    }
}

// ---------------- H2=256 persistent scan (layers 1,2), grid (16,8) ----------------
template<int LAYER>
__global__ void __launch_bounds__(256) scan256_kernel(const float* __restrict__ Whh)
{
    const int bi = blockIdx.x, jj = blockIdx.y;
    const int tid = threadIdx.x, lane = tid & 31, w = tid >> 5;
    const int b = lane & 15, jh = lane >> 4;
    const int jloc = w * 4 + jh * 2;
    const int j0 = jj * 32, b0 = bi * 16;
    const int HP = 260;

    extern __shared__ float sm[];
    float* Wsm = sm;               // [128 rows (g*32+jl)][256]
    float* hsm = sm + 128 * 256;   // [16][260]

    float* hbuf = (LAYER == 1) ? g_h1 : g_h2;
    const float* xg = g_xg1;
    int* flags = g_flags + ((LAYER == 1) ? 8192 : 12288) + bi * 256;

    for (int v = tid; v < 128 * 64; v += 256) {
        int r = v >> 6, kc = (v & 63) << 2;
        int grow = ((r >> 5) << 8) + j0 + (r & 31);
        *(float4*)&Wsm[r * 256 + kc] = *(const float4*)(Whh + (size_t)grow * 256 + kc);
    }
    __syncthreads();

    float c0 = 0.f, c1 = 0.f;
    for (int s = 0; s < 256; s++) {
        const int t = s;

        float2 xv[4];
        {
            const float* xr = xg + ((size_t)(t * 256 + b0 + b)) * 1024 + j0 + jloc;
#pragma unroll
            for (int g = 0; g < 4; g++) xv[g] = *(const float2*)(xr + (g << 8));
        }
        float gate[8];
#pragma unroll
        for (int g = 0; g < 4; g++) { gate[g] = xv[g].x; gate[4 + g] = xv[g].y; }

        if (s > 0) {
            if (tid == 0) { while (*(volatile int*)&flags[s - 1] < 8) { } }
            __syncthreads();
            for (int v = tid; v < 1024; v += 256) {
                int row = v >> 6, kc = (v & 63) << 2;
                *(float4*)&hsm[row * HP + kc] =
                    *(const float4*)(hbuf + ((size_t)((t - 1) * 256 + b0 + row)) * 256 + kc);
            }
            __syncthreads();

            unsigned long long acc[8];
#pragma unroll
            for (int i = 0; i < 8; i++) acc[i] = 0ull;

            const float* hrow = &hsm[b * HP];
#pragma unroll 2
            for (int k = 0; k < 256; k += 4) {
                ulonglong2 hv = *(const ulonglong2*)(hrow + k);
#pragma unroll
                for (int g = 0; g < 4; g++) {
#pragma unroll
                    for (int jp = 0; jp < 2; jp++) {
                        ulonglong2 wv = *(const ulonglong2*)&Wsm[((g << 5) + jloc + jp) * 256 + k];
                        fma2(acc[jp * 4 + g], wv.x, hv.x);
                        fma2(acc[jp * 4 + g], wv.y, hv.y);
                    }
                }
            }
#pragma unroll
            for (int i = 0; i < 8; i++) gate[i] += hsum2(acc[i]);
        }

        float2 ho;
        {
            float iv = sigf(gate[0]), fv = sigf(gate[1]);
            float gv = tanhf(gate[2]), ov = sigf(gate[3]);
            c0 = fv * c0 + iv * gv;
            ho.x = ov * tanhf(c0);
        }
        {
            float iv = sigf(gate[4]), fv = sigf(gate[5]);
            float gv = tanhf(gate[6]), ov = sigf(gate[7]);
            c1 = fv * c1 + iv * gv;
            ho.y = ov * tanhf(c1);
        }
        *(float2*)(hbuf + ((size_t)(t * 256 + b0 + b)) * 256 + j0 + jloc) = ho;

        __threadfence();
        __syncthreads();
        if (tid == 0) atomicAdd(&flags[s], 1);
    }
}

// ---------------- LayerNorm over last dim (256), warp per row ----------------
template<int WHICH>
__global__ void __launch_bounds__(256) ln_kernel(const float* __restrict__ gam,
                                                 const float* __restrict__ bet)
{
    const int warp = threadIdx.x >> 5, lane = threadIdx.x & 31;
    const size_t row = (size_t)blockIdx.x * 8 + warp;
    const float* x = (WHICH == 1) ? g_bl : g_h1;
    float* out = (WHICH == 1) ? g_bl : g_h1;
    const size_t base = row * 256 + lane * 8;

    float4 a0 = *(const float4*)(x + base);
    float4 a1 = *(const float4*)(x + base + 4);
    if (WHICH == 2) {
        float4 r0 = *(const float4*)(g_bl + base);
        float4 r1 = *(const float4*)(g_bl + base + 4);
        a0.x += r0.x; a0.y += r0.y; a0.z += r0.z; a0.w += r0.w;
        a1.x += r1.x; a1.y += r1.y; a1.z += r1.z; a1.w += r1.w;
    }
    float v[8] = {a0.x,a0.y,a0.z,a0.w,a1.x,a1.y,a1.z,a1.w};
    float s = 0.f;
#pragma unroll
    for (int i = 0; i < 8; i++) s += v[i];
#pragma unroll
    for (int o = 16; o; o >>= 1) s += __shfl_xor_sync(0xffffffffu, s, o);
    float mu = s * (1.f / 256.f);
    float ss = 0.f;
#pragma unroll
    for (int i = 0; i < 8; i++) { v[i] -= mu; ss += v[i] * v[i]; }
#pragma unroll
    for (int o = 16; o; o >>= 1) ss += __shfl_xor_sync(0xffffffffu, ss, o);
    float rs = rsqrtf(ss * (1.f / 256.f) + 1e-5f);
    const int c0 = lane * 8;
    float4 g0 = *(const float4*)(gam + c0), g1 = *(const float4*)(gam + c0 + 4);
    float4 b0 = *(const float4*)(bet + c0), b1 = *(const float4*)(bet + c0 + 4);
    float gg[8] = {g0.x,g0.y,g0.z,g0.w,g1.x,g1.y,g1.z,g1.w};
    float bb[8] = {b0.x,b0.y,b0.z,b0.w,b1.x,b1.y,b1.z,b1.w};
    float4 o0, o1;
    o0.x = v[0]*rs*gg[0]+bb[0]; o0.y = v[1]*rs*gg[1]+bb[1];
    o0.z = v[2]*rs*gg[2]+bb[2]; o0.w = v[3]*rs*gg[3]+bb[3];
    o1.x = v[4]*rs*gg[4]+bb[4]; o1.y = v[5]*rs*gg[5]+bb[5];
    o1.z = v[6]*rs*gg[6]+bb[6]; o1.w = v[7]*rs*gg[7]+bb[7];
    *(float4*)(out + base) = o0;
    *(float4*)(out + base + 4) = o1;
}

// ---------------- gather + affine + relu (auto int32/int64 idx) ----------------
__global__ void __launch_bounds__(256) gather_kernel(const int* __restrict__ idx32,
                                                     const float* __restrict__ bn_g,
                                                     const float* __restrict__ bn_b,
                                                     float* __restrict__ out)
{
    __shared__ int sidx;
    const int b = blockIdx.x, j = threadIdx.x;
    if (j < 32) {
        int v = idx32[2 * j + 1];
        unsigned m = __ballot_sync(0xffffffffu, v != 0);
        if (j == 0) sidx = (m == 0) ? idx32[2 * b] : idx32[b];
    }
    __syncthreads();
    const int t = sidx;
    float scale = rsqrtf(1.0f + 1e-5f);
    float y = g_h2[((size_t)(t * 256 + b)) * 256 + j] * scale * bn_g[j] + bn_b[j];
    out[(size_t)b * 256 + j] = fmaxf(y, 0.f);
}

// ---------------- launch ----------------
extern "C" void kernel_launch(void* const* d_in, const int* in_sizes, int n_in,
                              void* d_out, int out_size)
{
    const float* inp   = (const float*)d_in[0];
    const int*   idx   = (const int*)  d_in[1];
    const float* Wih_f = (const float*)d_in[2];
    const float* Whh_f = (const float*)d_in[3];
    const float* b_f   = (const float*)d_in[4];
    const float* Wih_r = (const float*)d_in[5];
    const float* Whh_r = (const float*)d_in[6];
    const float* b_r   = (const float*)d_in[7];
    const float* ln1_g = (const float*)d_in[8];
    const float* ln1_b = (const float*)d_in[9];
    const float* W1ih  = (const float*)d_in[10];
    const float* W1hh  = (const float*)d_in[11];
    const float* b1    = (const float*)d_in[12];
    const float* ln2_g = (const float*)d_in[13];
    const float* ln2_b = (const float*)d_in[14];
    const float* W2ih  = (const float*)d_in[15];
    const float* W2hh  = (const float*)d_in[16];
    const float* b2    = (const float*)d_in[17];
    const float* bn_g  = (const float*)d_in[18];
    const float* bn_b  = (const float*)d_in[19];
    float* out = (float*)d_out;

    cudaFuncSetAttribute(scan0_kernel,      cudaFuncAttributeMaxDynamicSharedMemorySize, 73984);
    cudaFuncSetAttribute(scan256_kernel<1>, cudaFuncAttributeMaxDynamicSharedMemorySize, 147712);
    cudaFuncSetAttribute(scan256_kernel<2>, cudaFuncAttributeMaxDynamicSharedMemorySize, 147712);

    zero_flags_kernel<<<64, 256>>>();
    mma_gemm<128, 512, 0><<<dim3(512, 4), 256>>>(inp, Wih_f, b_f);
    mma_gemm<128, 512, 1><<<dim3(512, 4), 256>>>(inp, Wih_r, b_r);
    scan0_kernel<<<dim3(16, 4, 2), 256, 73984>>>(Whh_f, Whh_r);
    ln_kernel<1><<<8192, 256>>>(ln1_g, ln1_b);
    mma_gemm<256, 1024, 2><<<dim3(512, 8), 256>>>(nullptr, W1ih, b1);
    scan256_kernel<1><<<dim3(16, 8), 256, 147712>>>(W1hh);
    ln_kernel<2><<<8192, 256>>>(ln2_g, ln2_b);
    mma_gemm<256, 1024, 3><<<dim3(512, 8), 256>>>(nullptr, W2ih, b2);
    scan256_kernel<2><<<dim3(16, 8), 256, 147712>>>(W2hh);
    gather_kernel<<<256, 256>>>(idx, bn_g, bn_b, out);
}

// round 10
// speedup vs baseline: 1.4934x; 1.4934x over previous
#include <cuda_runtime.h>
#include <math.h>

#define TT 256
#define BSZ 256

// ---------------- device scratch (no allocation APIs) ----------------
static __device__ float g_xg0f[33554432];   // [T*B][512]
static __device__ float g_xg0r[33554432];   // [T*B][512]
static __device__ float g_xg1 [67108864];   // [T*B][1024] (layer1, reused layer2)
static __device__ float g_bl  [16777216];   // [T*B][256]  bilstm h -> LN1 in place
static __device__ float g_h1  [16777216];   // [T*B][256]  layer1 h -> LN2 in place
static __device__ float g_h2  [16777216];   // [T*B][256]  layer2 h
static __device__ int   g_flags[16384];

__global__ void zero_flags_kernel() {
    int i = blockIdx.x * blockDim.x + threadIdx.x;
    if (i < 16384) g_flags[i] = 0;
}

// ---------------- tf32 helpers ----------------
__device__ __forceinline__ unsigned f2tf32(float x) {
    unsigned r;
    asm("cvt.rna.tf32.f32 %0, %1;" : "=r"(r) : "f"(x));
    return r;
}
__device__ __forceinline__ void split_tf32(float v, unsigned& hi, unsigned& lo) {
    hi = f2tf32(v);
    lo = f2tf32(v - __uint_as_float(hi));
}
__device__ __forceinline__ void mma_tf32(float c[4], const unsigned a[4], const unsigned b[2]) {
    asm volatile(
        "mma.sync.aligned.m16n8k8.row.col.f32.tf32.tf32.f32 "
        "{%0,%1,%2,%3}, {%4,%5,%6,%7}, {%8,%9}, {%0,%1,%2,%3};"
        : "+f"(c[0]), "+f"(c[1]), "+f"(c[2]), "+f"(c[3])
        : "r"(a[0]), "r"(a[1]), "r"(a[2]), "r"(a[3]), "r"(b[0]), "r"(b[1]));
}

// XOR-swizzled SMEM word offsets (conflict-free mma fragment loads)
#define OFF0(r, k) ((r) * 128 + (((((k) >> 2) ^ ((r) & 7))) << 2) + ((k) & 3))
#define OFF1(r, k) ((r) * 256 + (((((k) >> 2) ^ ((r) & 7))) << 2) + ((k) & 3))

// ---------------- tf32 tensor-core GEMM: C[M,N] = A[M,K] @ W[N,K]^T + bias ----
template<int K, int N, int MODE>
__global__ void __launch_bounds__(256) mma_gemm(const float* __restrict__ Ap,
                                                const float* __restrict__ W,
                                                const float* __restrict__ bias)
{
    __shared__ unsigned As[128 * 36];
    __shared__ unsigned Bs[128 * 36];
    const int tid = threadIdx.x, lane = tid & 31, wid = tid >> 5;
    const int warpM = wid >> 1, warpN = wid & 1;
    const int cRow = blockIdx.x, cCol = blockIdx.y;

    float acc[2][8][4];
#pragma unroll
    for (int mt = 0; mt < 2; mt++)
#pragma unroll
        for (int nt = 0; nt < 8; nt++)
#pragma unroll
            for (int i = 0; i < 4; i++) acc[mt][nt][i] = 0.f;

    for (int kt = 0; kt < K; kt += 32) {
#pragma unroll
        for (int i = 0; i < 4; i++) {
            int f = tid + i * 256;
            int row = f >> 3, kc = (f & 7) << 2;
            const float* ap;
            if (MODE <= 1) {
                int m = cRow * 128 + row;
                ap = Ap + ((size_t)(m & 255) * TT + (m >> 8)) * 128 + kt + kc;
            } else if (MODE == 2) {
                ap = g_bl + (size_t)(cRow * 128 + row) * K + kt + kc;
            } else {
                ap = g_h1 + (size_t)(cRow * 128 + row) * K + kt + kc;
            }
            float4 av = *(const float4*)ap;
            float4 bv = *(const float4*)(W + (size_t)(cCol * 128 + row) * K + kt + kc);
            unsigned* ad = &As[row * 36 + kc];
            ad[0] = f2tf32(av.x); ad[1] = f2tf32(av.y);
            ad[2] = f2tf32(av.z); ad[3] = f2tf32(av.w);
            unsigned* bd = &Bs[row * 36 + kc];
            bd[0] = f2tf32(bv.x); bd[1] = f2tf32(bv.y);
            bd[2] = f2tf32(bv.z); bd[3] = f2tf32(bv.w);
        }
        __syncthreads();

#pragma unroll
        for (int kk = 0; kk < 32; kk += 8) {
            const int k0 = kk + (lane & 3);
            unsigned a[2][4], b[8][2];
#pragma unroll
            for (int mt = 0; mt < 2; mt++) {
                int row = warpM * 32 + mt * 16 + (lane >> 2);
                a[mt][0] = As[row * 36 + k0];
                a[mt][1] = As[(row + 8) * 36 + k0];
                a[mt][2] = As[row * 36 + k0 + 4];
                a[mt][3] = As[(row + 8) * 36 + k0 + 4];
            }
#pragma unroll
            for (int nt = 0; nt < 8; nt++) {
                int col = warpN * 64 + nt * 8 + (lane >> 2);
                b[nt][0] = Bs[col * 36 + k0];
                b[nt][1] = Bs[col * 36 + k0 + 4];
            }
#pragma unroll
            for (int mt = 0; mt < 2; mt++)
#pragma unroll
                for (int nt = 0; nt < 8; nt++)
                    mma_tf32(acc[mt][nt], a[mt], b[nt]);
        }
        __syncthreads();
    }

    float* Cout = (MODE == 0) ? g_xg0f : (MODE == 1) ? g_xg0r : g_xg1;
#pragma unroll
    for (int nt = 0; nt < 8; nt++) {
        int c = cCol * 128 + warpN * 64 + nt * 8 + (lane & 3) * 2;
        float bx = bias[c], by = bias[c + 1];
#pragma unroll
        for (int mt = 0; mt < 2; mt++) {
            int r0 = cRow * 128 + warpM * 32 + mt * 16 + (lane >> 2);
            float2 o0 = {acc[mt][nt][0] + bx, acc[mt][nt][1] + by};
            float2 o1 = {acc[mt][nt][2] + bx, acc[mt][nt][3] + by};
            *(float2*)(Cout + (size_t)r0 * N + c)       = o0;
            *(float2*)(Cout + (size_t)(r0 + 8) * N + c) = o1;
        }
    }
}

__device__ __forceinline__ float sigf(float x) { return 1.f / (1.f + expf(-x)); }

// ---------------- layer0 persistent scan, H=128, grid (16,4,2) ----------------
// Tensor-core recurrence with 3-term tf32 split (Wh,Wl in SMEM once; h split/step).
// CTA: 16 batch x 32 j (128 gate cols, smem row = jl*4 + g). 8 warps x 2 n8-tiles.
__global__ void __launch_bounds__(256) scan0_kernel(const float* __restrict__ WhhF,
                                                    const float* __restrict__ WhhR)
{
    const int bi = blockIdx.x, jj = blockIdx.y, dir = blockIdx.z;
    const int tid = threadIdx.x, lane = tid & 31, w = tid >> 5;
    const int j0 = jj * 32, b0 = bi * 16;

    extern __shared__ unsigned smu[];
    unsigned* Wh = smu;                    // 128x128
    unsigned* Wl = Wh + 16384;
    unsigned* Hh = Wl + 16384;             // 16x128
    unsigned* Hl = Hh + 2048;
    float*    Gs = (float*)(Hl + 2048);    // [16][132]

    const float* Whh = dir ? WhhR : WhhF;
    const float* xg  = dir ? g_xg0r : g_xg0f;
    int* flags = g_flags + dir * 4096 + bi * 256;

    // convert + split W once: smem row r = jl*4 + g  <- global row g*128 + j0 + jl
#pragma unroll
    for (int i = 0; i < 16; i++) {
        int v = tid + i * 256;
        int r = v >> 5, k4 = v & 31;
        int jl = r >> 2, g = r & 3;
        float4 wv = *(const float4*)(Whh + (size_t)(g * 128 + j0 + jl) * 128 + k4 * 4);
        int so = r * 128 + ((k4 ^ (r & 7)) << 2);
        unsigned h0,l0,h1,l1,h2,l2,h3,l3;
        split_tf32(wv.x, h0, l0); split_tf32(wv.y, h1, l1);
        split_tf32(wv.z, h2, l2); split_tf32(wv.w, h3, l3);
        *(uint4*)&Wh[so] = make_uint4(h0, h1, h2, h3);
        *(uint4*)&Wl[so] = make_uint4(l0, l1, l2, l3);
    }
    __syncthreads();

    const int nt0 = w * 2;             // warp's two n8 tiles (16 total)
    const int bl = tid >> 4;           // 0..15 batch row for cell update
    const int jlA = tid & 15;          // cells (bl, jlA) and (bl, jlA+16)
    float cA = 0.f, cB = 0.f;

    for (int s = 0; s < 256; s++) {
        const int t = dir ? (255 - s) : s;

        // prefetch xg (hidden behind flag spin + staging)
        float xa[4], xb[4];
        {
            const float* xr = xg + ((size_t)(t * 256 + b0 + bl)) * 512 + j0;
#pragma unroll
            for (int g = 0; g < 4; g++) { xa[g] = xr[(g << 7) + jlA]; xb[g] = xr[(g << 7) + jlA + 16]; }
        }

        if (s > 0) {
            const int tp = dir ? (t + 1) : (t - 1);
            if (tid == 0) { while (*(volatile int*)&flags[s - 1] < 4) { } }
            __syncthreads();
            // stage + split h_{t-1}[16][128]
#pragma unroll
            for (int i = 0; i < 2; i++) {
                int v = tid + i * 256;
                int r = v >> 5, k4 = v & 31;
                float4 hv = *(const float4*)(g_bl + ((size_t)(tp * 256 + b0 + r)) * 256 + (dir << 7) + k4 * 4);
                int so = r * 128 + ((k4 ^ (r & 7)) << 2);
                unsigned h0,l0,h1,l1,h2,l2,h3,l3;
                split_tf32(hv.x, h0, l0); split_tf32(hv.y, h1, l1);
                split_tf32(hv.z, h2, l2); split_tf32(hv.w, h3, l3);
                *(uint4*)&Hh[so] = make_uint4(h0, h1, h2, h3);
                *(uint4*)&Hl[so] = make_uint4(l0, l1, l2, l3);
            }
            __syncthreads();

            float acc[2][4] = {{0.f,0.f,0.f,0.f},{0.f,0.f,0.f,0.f}};
#pragma unroll
            for (int ks = 0; ks < 16; ks++) {
                const int ka = ks * 8 + (lane & 3);
                const int ra = lane >> 2;
                unsigned ahh[4], ahl[4];
                ahh[0] = Hh[OFF0(ra, ka)];     ahh[1] = Hh[OFF0(ra + 8, ka)];
                ahh[2] = Hh[OFF0(ra, ka + 4)]; ahh[3] = Hh[OFF0(ra + 8, ka + 4)];
                ahl[0] = Hl[OFF0(ra, ka)];     ahl[1] = Hl[OFF0(ra + 8, ka)];
                ahl[2] = Hl[OFF0(ra, ka + 4)]; ahl[3] = Hl[OFF0(ra + 8, ka + 4)];
#pragma unroll
                for (int n = 0; n < 2; n++) {
                    const int nr = (nt0 + n) * 8 + (lane >> 2);
                    unsigned bh[2]  = { Wh[OFF0(nr, ka)], Wh[OFF0(nr, ka + 4)] };
                    unsigned blo[2] = { Wl[OFF0(nr, ka)], Wl[OFF0(nr, ka + 4)] };
                    mma_tf32(acc[n], ahh, bh);
                    mma_tf32(acc[n], ahh, blo);
                    mma_tf32(acc[n], ahl, bh);
                }
            }
#pragma unroll
            for (int n = 0; n < 2; n++) {
                int col = (nt0 + n) * 8 + 2 * (lane & 3);
                int r = lane >> 2;
                Gs[r * 132 + col]           = acc[n][0];
                Gs[r * 132 + col + 1]       = acc[n][1];
                Gs[(r + 8) * 132 + col]     = acc[n][2];
                Gs[(r + 8) * 132 + col + 1] = acc[n][3];
            }
            __syncthreads();
        }

        float gA[4] = {0.f,0.f,0.f,0.f}, gB[4] = {0.f,0.f,0.f,0.f};
        if (s > 0) {
            *(float4*)gA = *(const float4*)&Gs[bl * 132 + jlA * 4];
            *(float4*)gB = *(const float4*)&Gs[bl * 132 + (jlA + 16) * 4];
        }
        float* hrow = g_bl + ((size_t)(t * 256 + b0 + bl)) * 256 + (dir << 7) + j0;
        {
            float iv = sigf(gA[0] + xa[0]), fv = sigf(gA[1] + xa[1]);
            float gv = tanhf(gA[2] + xa[2]), ov = sigf(gA[3] + xa[3]);
            cA = fv * cA + iv * gv;
            hrow[jlA] = ov * tanhf(cA);
        }
        {
            float iv = sigf(gB[0] + xb[0]), fv = sigf(gB[1] + xb[1]);
            float gv = tanhf(gB[2] + xb[2]), ov = sigf(gB[3] + xb[3]);
            cB = fv * cB + iv * gv;
            hrow[jlA + 16] = ov * tanhf(cB);
        }
        __threadfence();
        __syncthreads();
        if (tid == 0) atomicAdd(&flags[s], 1);
    }
}

// ---------------- H2=256 persistent scan (layers 1,2), grid (8,16) -------------
// CTA: 32 batch x 16 j (64 gate cols), K=256. 8 warps: m-tile = w&1, n-tiles 2(w>>1)+{0,1}.
template<int LAYER>
__global__ void __launch_bounds__(256) scan256_kernel(const float* __restrict__ Whh)
{
    const int bi = blockIdx.x;     // 0..7
    const int jj = blockIdx.y;     // 0..15
    const int tid = threadIdx.x, lane = tid & 31, w = tid >> 5;
    const int j0 = jj * 16, b0 = bi * 32;

    extern __shared__ unsigned smu[];
    unsigned* Wh = smu;                    // 64x256
    unsigned* Wl = Wh + 16384;
    unsigned* Hh = Wl + 16384;             // 32x256
    unsigned* Hl = Hh + 8192;
    float*    Gs = (float*)(Hl + 8192);    // [32][68]

    float* hbuf = (LAYER == 1) ? g_h1 : g_h2;
    int* flags = g_flags + ((LAYER == 1) ? 8192 : 12288) + bi * 256;

    // convert + split W once: smem row r = jl*4 + g <- global row g*256 + j0 + jl
#pragma unroll
    for (int i = 0; i < 16; i++) {
        int v = tid + i * 256;
        int r = v >> 6, k4 = v & 63;
        int jl = r >> 2, g = r & 3;
        float4 wv = *(const float4*)(Whh + (size_t)(g * 256 + j0 + jl) * 256 + k4 * 4);
        int so = r * 256 + ((k4 ^ (r & 7)) << 2);
        unsigned h0,l0,h1,l1,h2,l2,h3,l3;
        split_tf32(wv.x, h0, l0); split_tf32(wv.y, h1, l1);
        split_tf32(wv.z, h2, l2); split_tf32(wv.w, h3, l3);
        *(uint4*)&Wh[so] = make_uint4(h0, h1, h2, h3);
        *(uint4*)&Wl[so] = make_uint4(l0, l1, l2, l3);
    }
    __syncthreads();

    const int m0 = (w & 1) * 16;
    const int nt0 = (w >> 1) * 2;
    const int bl = tid >> 4;        // 0..15 ; cells (bl, jl) and (bl+16, jl)
    const int jl = tid & 15;
    float cA = 0.f, cB = 0.f;

    for (int s = 0; s < 256; s++) {
        const int t = s;

        float xa[4], xb[4];
        {
            const float* xrA = g_xg1 + ((size_t)(t * 256 + b0 + bl)) * 1024 + j0 + jl;
            const float* xrB = g_xg1 + ((size_t)(t * 256 + b0 + bl + 16)) * 1024 + j0 + jl;
#pragma unroll
            for (int g = 0; g < 4; g++) { xa[g] = xrA[g << 8]; xb[g] = xrB[g << 8]; }
        }

        if (s > 0) {
            if (tid == 0) { while (*(volatile int*)&flags[s - 1] < 16) { } }
            __syncthreads();
#pragma unroll
            for (int i = 0; i < 8; i++) {
                int v = tid + i * 256;
                int r = v >> 6, k4 = v & 63;
                float4 hv = *(const float4*)(hbuf + ((size_t)((t - 1) * 256 + b0 + r)) * 256 + k4 * 4);
                int so = r * 256 + ((k4 ^ (r & 7)) << 2);
                unsigned h0,l0,h1,l1,h2,l2,h3,l3;
                split_tf32(hv.x, h0, l0); split_tf32(hv.y, h1, l1);
                split_tf32(hv.z, h2, l2); split_tf32(hv.w, h3, l3);
                *(uint4*)&Hh[so] = make_uint4(h0, h1, h2, h3);
                *(uint4*)&Hl[so] = make_uint4(l0, l1, l2, l3);
            }
            __syncthreads();

            float acc[2][4] = {{0.f,0.f,0.f,0.f},{0.f,0.f,0.f,0.f}};
#pragma unroll
            for (int ks = 0; ks < 32; ks++) {
                const int ka = ks * 8 + (lane & 3);
                const int ra = m0 + (lane >> 2);
                unsigned ahh[4], ahl[4];
                ahh[0] = Hh[OFF1(ra, ka)];     ahh[1] = Hh[OFF1(ra + 8, ka)];
                ahh[2] = Hh[OFF1(ra, ka + 4)]; ahh[3] = Hh[OFF1(ra + 8, ka + 4)];
                ahl[0] = Hl[OFF1(ra, ka)];     ahl[1] = Hl[OFF1(ra + 8, ka)];
                ahl[2] = Hl[OFF1(ra, ka + 4)]; ahl[3] = Hl[OFF1(ra + 8, ka + 4)];
#pragma unroll
                for (int n = 0; n < 2; n++) {
                    const int nr = (nt0 + n) * 8 + (lane >> 2);
                    unsigned bh[2]  = { Wh[OFF1(nr, ka)], Wh[OFF1(nr, ka + 4)] };
                    unsigned blo[2] = { Wl[OFF1(nr, ka)], Wl[OFF1(nr, ka + 4)] };
                    mma_tf32(acc[n], ahh, bh);
                    mma_tf32(acc[n], ahh, blo);
                    mma_tf32(acc[n], ahl, bh);
                }
            }
#pragma unroll
            for (int n = 0; n < 2; n++) {
                int col = (nt0 + n) * 8 + 2 * (lane & 3);
                int r = m0 + (lane >> 2);
                Gs[r * 68 + col]           = acc[n][0];
                Gs[r * 68 + col + 1]       = acc[n][1];
                Gs[(r + 8) * 68 + col]     = acc[n][2];
                Gs[(r + 8) * 68 + col + 1] = acc[n][3];
            }
            __syncthreads();
        }

        float gA[4] = {0.f,0.f,0.f,0.f}, gB[4] = {0.f,0.f,0.f,0.f};
        if (s > 0) {
            *(float4*)gA = *(const float4*)&Gs[bl * 68 + jl * 4];
            *(float4*)gB = *(const float4*)&Gs[(bl + 16) * 68 + jl * 4];
        }
        {
            float iv = sigf(gA[0] + xa[0]), fv = sigf(gA[1] + xa[1]);
            float gv = tanhf(gA[2] + xa[2]), ov = sigf(gA[3] + xa[3]);
            cA = fv * cA + iv * gv;
            hbuf[((size_t)(t * 256 + b0 + bl)) * 256 + j0 + jl] = ov * tanhf(cA);
        }
        {
            float iv = sigf(gB[0] + xb[0]), fv = sigf(gB[1] + xb[1]);
            float gv = tanhf(gB[2] + xb[2]), ov = sigf(gB[3] + xb[3]);
            cB = fv * cB + iv * gv;
            hbuf[((size_t)(t * 256 + b0 + bl + 16)) * 256 + j0 + jl] = ov * tanhf(cB);
        }
        __threadfence();
        __syncthreads();
        if (tid == 0) atomicAdd(&flags[s], 1);
    }
}

// ---------------- LayerNorm over last dim (256), warp per row ----------------
template<int WHICH>
__global__ void __launch_bounds__(256) ln_kernel(const float* __restrict__ gam,
                                                 const float* __restrict__ bet)
{
    const int warp = threadIdx.x >> 5, lane = threadIdx.x & 31;
    const size_t row = (size_t)blockIdx.x * 8 + warp;
    const float* x = (WHICH == 1) ? g_bl : g_h1;
    float* out = (WHICH == 1) ? g_bl : g_h1;
    const size_t base = row * 256 + lane * 8;

    float4 a0 = *(const float4*)(x + base);
    float4 a1 = *(const float4*)(x + base + 4);
    if (WHICH == 2) {
        float4 r0 = *(const float4*)(g_bl + base);
        float4 r1 = *(const float4*)(g_bl + base + 4);
        a0.x += r0.x; a0.y += r0.y; a0.z += r0.z; a0.w += r0.w;
        a1.x += r1.x; a1.y += r1.y; a1.z += r1.z; a1.w += r1.w;
    }
    float v[8] = {a0.x,a0.y,a0.z,a0.w,a1.x,a1.y,a1.z,a1.w};
    float s = 0.f;
#pragma unroll
    for (int i = 0; i < 8; i++) s += v[i];
#pragma unroll
    for (int o = 16; o; o >>= 1) s += __shfl_xor_sync(0xffffffffu, s, o);
    float mu = s * (1.f / 256.f);
    float ss = 0.f;
#pragma unroll
    for (int i = 0; i < 8; i++) { v[i] -= mu; ss += v[i] * v[i]; }
#pragma unroll
    for (int o = 16; o; o >>= 1) ss += __shfl_xor_sync(0xffffffffu, ss, o);
    float rs = rsqrtf(ss * (1.f / 256.f) + 1e-5f);
    const int c0 = lane * 8;
    float4 g0 = *(const float4*)(gam + c0), g1 = *(const float4*)(gam + c0 + 4);
    float4 b0 = *(const float4*)(bet + c0), b1 = *(const float4*)(bet + c0 + 4);
    float gg[8] = {g0.x,g0.y,g0.z,g0.w,g1.x,g1.y,g1.z,g1.w};
    float bb[8] = {b0.x,b0.y,b0.z,b0.w,b1.x,b1.y,b1.z,b1.w};
    float4 o0, o1;
    o0.x = v[0]*rs*gg[0]+bb[0]; o0.y = v[1]*rs*gg[1]+bb[1];
    o0.z = v[2]*rs*gg[2]+bb[2]; o0.w = v[3]*rs*gg[3]+bb[3];
    o1.x = v[4]*rs*gg[4]+bb[4]; o1.y = v[5]*rs*gg[5]+bb[5];
    o1.z = v[6]*rs*gg[6]+bb[6]; o1.w = v[7]*rs*gg[7]+bb[7];
    *(float4*)(out + base) = o0;
    *(float4*)(out + base + 4) = o1;
}

// ---------------- gather + affine + relu (auto int32/int64 idx) ----------------
__global__ void __launch_bounds__(256) gather_kernel(const int* __restrict__ idx32,
                                                     const float* __restrict__ bn_g,
                                                     const float* __restrict__ bn_b,
                                                     float* __restrict__ out)
{
    __shared__ int sidx;
    const int b = blockIdx.x, j = threadIdx.x;
    if (j < 32) {
        int v = idx32[2 * j + 1];
        unsigned m = __ballot_sync(0xffffffffu, v != 0);
        if (j == 0) sidx = (m == 0) ? idx32[2 * b] : idx32[b];
    }
    __syncthreads();
    const int t = sidx;
    float scale = rsqrtf(1.0f + 1e-5f);
    float y = g_h2[((size_t)(t * 256 + b)) * 256 + j] * scale * bn_g[j] + bn_b[j];
    out[(size_t)b * 256 + j] = fmaxf(y, 0.f);
}

// ---------------- launch ----------------
extern "C" void kernel_launch(void* const* d_in, const int* in_sizes, int n_in,
                              void* d_out, int out_size)
{
    const float* inp   = (const float*)d_in[0];
    const int*   idx   = (const int*)  d_in[1];
    const float* Wih_f = (const float*)d_in[2];
    const float* Whh_f = (const float*)d_in[3];
    const float* b_f   = (const float*)d_in[4];
    const float* Wih_r = (const float*)d_in[5];
    const float* Whh_r = (const float*)d_in[6];
    const float* b_r   = (const float*)d_in[7];
    const float* ln1_g = (const float*)d_in[8];
    const float* ln1_b = (const float*)d_in[9];
    const float* W1ih  = (const float*)d_in[10];
    const float* W1hh  = (const float*)d_in[11];
    const float* b1    = (const float*)d_in[12];
    const float* ln2_g = (const float*)d_in[13];
    const float* ln2_b = (const float*)d_in[14];
    const float* W2ih  = (const float*)d_in[15];
    const float* W2hh  = (const float*)d_in[16];
    const float* b2    = (const float*)d_in[17];
    const float* bn_g  = (const float*)d_in[18];
    const float* bn_b  = (const float*)d_in[19];
    float* out = (float*)d_out;

    const int SM0 = (16384 * 2 + 2048 * 2) * 4 + 16 * 132 * 4;    // 155904
    const int SM1 = (16384 * 2 + 8192 * 2) * 4 + 32 * 68 * 4;     // 205312
    cudaFuncSetAttribute(scan0_kernel,      cudaFuncAttributeMaxDynamicSharedMemorySize, SM0);
    cudaFuncSetAttribute(scan256_kernel<1>, cudaFuncAttributeMaxDynamicSharedMemorySize, SM1);
    cudaFuncSetAttribute(scan256_kernel<2>, cudaFuncAttributeMaxDynamicSharedMemorySize, SM1);

    zero_flags_kernel<<<64, 256>>>();
    mma_gemm<128, 512, 0><<<dim3(512, 4), 256>>>(inp, Wih_f, b_f);
    mma_gemm<128, 512, 1><<<dim3(512, 4), 256>>>(inp, Wih_r, b_r);
    scan0_kernel<<<dim3(16, 4, 2), 256, SM0>>>(Whh_f, Whh_r);
    ln_kernel<1><<<8192, 256>>>(ln1_g, ln1_b);
    mma_gemm<256, 1024, 2><<<dim3(512, 8), 256>>>(nullptr, W1ih, b1);
    scan256_kernel<1><<<dim3(8, 16), 256, SM1>>>(W1hh);
    ln_kernel<2><<<8192, 256>>>(ln2_g, ln2_b);
    mma_gemm<256, 1024, 3><<<dim3(512, 8), 256>>>(nullptr, W2ih, b2);
    scan256_kernel<2><<<dim3(8, 16), 256, SM1>>>(W2hh);
    gather_kernel<<<256, 256>>>(idx, bn_g, bn_b, out);
}